// round 12
// baseline (speedup 1.0000x reference)
#include <cuda_runtime.h>
#include <cuda_fp16.h>
#include <cstdint>

#define B_ROWS   131072
#define TOT_ROWS 262144

// ---------------- scratch (device globals; no allocations) ----------------
__device__ __half  g_a0[(size_t)TOT_ROWS * 64];
__device__ __half  g_actA[(size_t)TOT_ROWS * 512];
__device__ __half  g_actB[(size_t)TOT_ROWS * 512];
__device__ __half  g_wt0[512 * 64];
__device__ __half  g_wt1[512 * 512];
__device__ __half  g_wt2[512 * 512];
__device__ __half  g_wt3[512 * 512];
__device__ float4  g_statA[(size_t)TOT_ROWS * 8];   // 16 float2 partials per row
__device__ float4  g_statB[(size_t)TOT_ROWS * 8];
__device__ float   g_u1[512], g_c1[512];
__device__ float   g_u2[512], g_c2[512];
__device__ float   g_u3[512], g_c3[512];
__device__ float2  g_iqePart[(size_t)B_ROWS * 4];   // (sum4, max4) per (row, colcta)

// ---------------- PTX helpers ----------------
static __device__ __forceinline__ uint32_t smem_u32(const void* p) {
    uint32_t a;
    asm("{ .reg .u64 t; cvta.to.shared.u64 t, %1; cvt.u32.u64 %0, t; }" : "=r"(a) : "l"(p));
    return a;
}
static __device__ __forceinline__ void cp16(uint32_t dst, const void* src) {
    asm volatile("cp.async.cg.shared.global [%0], [%1], 16;" :: "r"(dst), "l"(src));
}
static __device__ __forceinline__ void ldm_x4(uint32_t (&r)[4], uint32_t addr) {
    asm volatile("ldmatrix.sync.aligned.m8n8.x4.shared.b16 {%0,%1,%2,%3}, [%4];"
                 : "=r"(r[0]), "=r"(r[1]), "=r"(r[2]), "=r"(r[3]) : "r"(addr));
}
// fp16-accumulate HMMA: 2x rate of f32-acc on sm_103 (rt 8 vs 16)
static __device__ __forceinline__ void mma_f16h(uint32_t (&d)[2], const uint32_t (&a)[4],
                                                uint32_t b0, uint32_t b1) {
    asm volatile("mma.sync.aligned.m16n8k16.row.col.f16.f16.f16.f16 "
                 "{%0,%1}, {%2,%3,%4,%5}, {%6,%7}, {%0,%1};"
                 : "+r"(d[0]), "+r"(d[1])
                 : "r"(a[0]), "r"(a[1]), "r"(a[2]), "r"(a[3]), "r"(b0), "r"(b1));
}
// gelu(x) = x * sigmoid(2 * sqrt(2/pi) * (x + 0.044715 x^3))   (tanh form)
static __device__ __forceinline__ float gelu_f(float x) {
    float u = 0.7978845608028654f * x * (1.0f + 0.044715f * x * x);
    return x / (1.0f + __expf(-2.0f * u));
}
// swizzled byte offset within a [rows][32 f16 = 64B] tile (conflict-free ldmatrix)
static __device__ __forceinline__ uint32_t swz(int row, int seg) {
    return (uint32_t)(row * 64 + ((seg ^ ((row >> 1) & 3)) << 4));
}

// ---------------- smem layout ----------------
// mainloop: 6-slot ring, slot (12KB): A @ 0 (4KB: 64 rows x 64B), W @ +4096 (8KB)
// paired epilogue: phi tile [64][132] f32 (33792B) + fold arrays (reuses ring)
#define SLOT_BYTES 12288
#define SMEM_BYTES (6 * SLOT_BYTES + 128)

// ---------------- fp16-acc MMA GEMM with folded LayerNorm ----------------
// CTA: 64 rows x 128 cols, 256 threads, warp grid 2(m) x 4(n), warp tile 32x32.
// occ 2. fp16 accumulators per 2-stage chunk (K=64), promoted to fp32 each
// chunk (error ~3e-4 z-level/layer, damped by LN). Ring of 6 K=32 slots, one
// barrier per two slots. All addresses precomputed; h=1 offsets = h0 ^ 32.
// FOLD: output = inv*(g@W'') - (m*inv)*u + c.
// ACT:  gelu, fp16 activation out + per-row partial stats.
// PAIRED (final layer): local rows 0-31 = phi_s, 32-63 = phi_g of the SAME 32
// batch rows; epilogue computes IQE per (pair, component) in-CTA.
template<int KDIM, bool ACT, bool FOLD, bool PAIRED>
__global__ __launch_bounds__(256, 2)
void gemm_kernel(const __half* __restrict__ Aact, const __half* __restrict__ Wt,
                 const float* __restrict__ uvec, const float* __restrict__ cvec,
                 const float4* __restrict__ statsIn, float2* __restrict__ statsOut,
                 __half* __restrict__ Oact, float2* __restrict__ iqePart)
{
    extern __shared__ char smraw[];
    char* smal = (char*)(((uintptr_t)smraw + 127) & ~(uintptr_t)127);
    const uint32_t sb = smem_u32(smal);

    const int tid  = threadIdx.x;
    const int lane = tid & 31;
    const int wid  = tid >> 5;
    const int wm   = wid >> 2;                 // 0..1 -> rows wm*32
    const int wn   = wid & 3;                  // 0..3 -> cols wn*32
    const int rowTile = blockIdx.x >> 2;
    const int colcta  = blockIdx.x & 3;
    const int row0 = PAIRED ? rowTile * 32 : rowTile * 64;
    const int col0 = colcta * 128;

    constexpr int NS = KDIM / 32;              // 2 or 16

    float facc[2][4][4];
#pragma unroll
    for (int mt = 0; mt < 2; mt++)
#pragma unroll
        for (int nt = 0; nt < 4; nt++)
#pragma unroll
            for (int j = 0; j < 4; j++) facc[mt][nt][j] = 0.f;

    // -------- precomputed loader state --------
    const int rA  = tid >> 2;                  // 0..63
    const int sgA = tid & 3;
    const uint32_t dstA  = swz(rA, sgA);
    const uint32_t dstW0 = 4096u + dstA;
    const uint32_t dstW1 = 4096u + swz(rA + 64, sgA);
    size_t growA;
    if constexpr (PAIRED)
        growA = (rA < 32) ? (size_t)(row0 + rA) : (size_t)B_ROWS + row0 + (rA - 32);
    else
        growA = (size_t)(row0 + rA);
    const __half* gA  = Aact + growA * KDIM + sgA * 8;
    const __half* gW0 = Wt + (size_t)(col0 + rA) * KDIM + sgA * 8;
    const __half* gW1 = gW0 + (size_t)64 * KDIM;

    // -------- precomputed ldmatrix offsets (h=1 = h0 ^ 32) --------
    const int ar   = lane & 15;
    const int aseg = lane >> 4;
    const int br   = (lane & 7) + ((lane >> 4) << 3);
    const int bseg = (lane >> 3) & 1;
    uint32_t offA[2], offB[2];
#pragma unroll
    for (int mt = 0; mt < 2; mt++) offA[mt] = swz(wm * 32 + mt * 16 + ar, aseg);
#pragma unroll
    for (int p = 0; p < 2; p++)    offB[p]  = 4096u + swz(wn * 32 + p * 16 + br, bseg);

#define LOAD_SLOT(slot)                                                     \
    do {                                                                    \
        uint32_t stb_ = sb + (uint32_t)(slot) * SLOT_BYTES;                 \
        cp16(stb_ + dstA, gA);                                              \
        cp16(stb_ + dstW0, gW0); cp16(stb_ + dstW1, gW1);                   \
        asm volatile("cp.async.commit_group;");                             \
        gA += 32; gW0 += 32; gW1 += 32;                                     \
    } while (0)

    // prologue: 4 groups (empty commits pad when NS < 4)
#pragma unroll
    for (int s = 0; s < 4; s++) {
        if (s < NS) LOAD_SLOT(s);
        else        asm volatile("cp.async.commit_group;");
    }

    int cslot = 0;
    int lslot = 4;
#pragma unroll 1
    for (int it = 0; it < NS / 2; it++) {
        asm volatile("cp.async.wait_group 2;");
        __syncthreads();

        const int s4 = 2 * it + 4;
        if (s4 < NS)     LOAD_SLOT(lslot);
        else             asm volatile("cp.async.commit_group;");
        lslot = (lslot + 1 == 6) ? 0 : lslot + 1;
        if (s4 + 1 < NS) LOAD_SLOT(lslot);
        else             asm volatile("cp.async.commit_group;");
        lslot = (lslot + 1 == 6) ? 0 : lslot + 1;

        // fp16 accumulators for this 2-stage chunk (K=64)
        uint32_t hacc[2][4][2];
#pragma unroll
        for (int mt = 0; mt < 2; mt++)
#pragma unroll
            for (int nt = 0; nt < 4; nt++) { hacc[mt][nt][0] = 0u; hacc[mt][nt][1] = 0u; }

#pragma unroll
        for (int u = 0; u < 2; u++) {
            const uint32_t stb = sb + (uint32_t)cslot * SLOT_BYTES;
#pragma unroll
            for (int h = 0; h < 2; h++) {
                const uint32_t hb = (uint32_t)h << 5;
                uint32_t a[2][4], b[2][4];
#pragma unroll
                for (int mt = 0; mt < 2; mt++) ldm_x4(a[mt], stb + (offA[mt] ^ hb));
#pragma unroll
                for (int p = 0; p < 2; p++)    ldm_x4(b[p],  stb + (offB[p]  ^ hb));
#pragma unroll
                for (int p = 0; p < 2; p++)
#pragma unroll
                    for (int q = 0; q < 2; q++)
#pragma unroll
                        for (int mt = 0; mt < 2; mt++)
                            mma_f16h(hacc[mt][2 * p + q], a[mt], b[p][2 * q], b[p][2 * q + 1]);
            }
            cslot = (cslot + 1 == 6) ? 0 : cslot + 1;
        }

        // promote chunk fp16 sums into persistent fp32 sums
#pragma unroll
        for (int mt = 0; mt < 2; mt++)
#pragma unroll
            for (int nt = 0; nt < 4; nt++) {
                float2 f0 = __half22float2(*reinterpret_cast<__half2*>(&hacc[mt][nt][0]));
                float2 f1 = __half22float2(*reinterpret_cast<__half2*>(&hacc[mt][nt][1]));
                facc[mt][nt][0] += f0.x;
                facc[mt][nt][1] += f0.y;
                facc[mt][nt][2] += f1.x;
                facc[mt][nt][3] += f1.y;
            }
    }
#undef LOAD_SLOT
    __syncthreads();   // release ring smem for epilogue

    // ---------------- epilogue ----------------
    float* base = (float*)smal;
    float* sInv = PAIRED ? (float*)(smal + 33792) : base;   // [64]
    float* sMi  = sInv + 64;                                 // [64]
    float* sU   = sMi + 64;                                  // [128]
    float* sC   = sU + 128;                                  // [128]

    if constexpr (FOLD) {
        if (tid < 64) {
            size_t grow;
            if constexpr (PAIRED)
                grow = (tid < 32) ? (size_t)(row0 + tid)
                                  : (size_t)B_ROWS + row0 + (tid - 32);
            else
                grow = (size_t)(row0 + tid);
            const float4* sp = statsIn + grow * 8;
            float ss = 0.f, sq = 0.f;
#pragma unroll
            for (int i = 0; i < 8; i++) {
                float4 v = sp[i];
                ss += v.x + v.z;
                sq += v.y + v.w;
            }
            float m   = ss * (1.0f / 512.0f);
            float var = fmaxf(sq * (1.0f / 512.0f) - m * m, 0.0f);
            float inv = rsqrtf(var + 1e-6f);
            sInv[tid] = inv;
            sMi[tid]  = m * inv;
        }
    }
    if (tid >= 128) {
        sU[tid - 128] = FOLD ? uvec[col0 + tid - 128] : 0.0f;
        sC[tid - 128] = cvec[col0 + tid - 128];
    }
    __syncthreads();

#pragma unroll
    for (int mt = 0; mt < 2; mt++) {
#pragma unroll
        for (int dp = 0; dp < 2; dp++) {
            const int rl   = wm * 32 + mt * 16 + dp * 8 + (lane >> 2);
            const float inv = FOLD ? sInv[rl] : 1.0f;
            const float mi  = FOLD ? sMi[rl]  : 0.0f;
            float gs = 0.f, gq = 0.f;
            size_t grow = (size_t)(row0 + rl);   // used by ACT path only
#pragma unroll
            for (int nt = 0; nt < 4; nt++) {
                const int cl = wn * 32 + nt * 8 + 2 * (lane & 3);
                float z0 = inv * facc[mt][nt][2 * dp + 0] - mi * sU[cl]     + sC[cl];
                float z1 = inv * facc[mt][nt][2 * dp + 1] - mi * sU[cl + 1] + sC[cl + 1];
                if constexpr (PAIRED) {
                    // stage phi in [row][i][comp] layout: conflict-free comp gathers
                    base[rl * 132 + (cl & 31) * 4 + (cl >> 5)]       = z0;
                    base[rl * 132 + ((cl & 31) + 1) * 4 + (cl >> 5)] = z1;
                } else if constexpr (ACT) {
                    float g0 = gelu_f(z0), g1 = gelu_f(z1);
                    gs += g0 + g1;
                    gq += g0 * g0 + g1 * g1;
                    __half2 hv = __floats2half2_rn(g0, g1);
                    *(__half2*)(Oact + grow * 512 + col0 + cl) = hv;
                }
            }
            if constexpr (ACT && !PAIRED) {
                gs += __shfl_xor_sync(0xffffffffu, gs, 1);
                gs += __shfl_xor_sync(0xffffffffu, gs, 2);
                gq += __shfl_xor_sync(0xffffffffu, gq, 1);
                gq += __shfl_xor_sync(0xffffffffu, gq, 2);
                if ((lane & 3) == 0)
                    statsOut[grow * 16 + (size_t)(colcta * 4 + wn)] = make_float2(gs, gq);
            }
        }
    }

    if constexpr (PAIRED) {
        __syncthreads();
        if (tid < 128) {
            // one thread per (pair row r, component comp)
            const int r    = tid >> 2;       // 0..31
            const int comp = tid & 3;
            const float* xs  = base + r * 132 + comp;
            const float* gs_ = base + (32 + r) * 132 + comp;
            float X[32], Y[32];
#pragma unroll
            for (int i = 0; i < 32; i++) {
                float xv = xs[i * 4];
                X[i] = xv;
                Y[i] = fmaxf(xv, gs_[i * 4]);
            }
#define BSTEP(V, KK, J)                                                   \
            _Pragma("unroll")                                             \
            for (int i = 0; i < 32; i++) {                                \
                int l = i ^ (J);                                          \
                if (l > i) {                                              \
                    bool up = ((i & (KK)) == 0);                          \
                    float a_ = V[i], b_ = V[l];                           \
                    float lo = fminf(a_, b_), hi = fmaxf(a_, b_);         \
                    V[i] = up ? lo : hi;  V[l] = up ? hi : lo;            \
                }                                                         \
            }
            BSTEP(X,2,1) BSTEP(X,4,2) BSTEP(X,4,1) BSTEP(X,8,4) BSTEP(X,8,2) BSTEP(X,8,1)
            BSTEP(X,16,8) BSTEP(X,16,4) BSTEP(X,16,2) BSTEP(X,16,1)
            BSTEP(X,32,16) BSTEP(X,32,8) BSTEP(X,32,4) BSTEP(X,32,2) BSTEP(X,32,1)
            BSTEP(Y,2,1) BSTEP(Y,4,2) BSTEP(Y,4,1) BSTEP(Y,8,4) BSTEP(Y,8,2) BSTEP(Y,8,1)
            BSTEP(Y,16,8) BSTEP(Y,16,4) BSTEP(Y,16,2) BSTEP(Y,16,1)
            BSTEP(Y,32,16) BSTEP(Y,32,8) BSTEP(Y,32,4) BSTEP(Y,32,2) BSTEP(Y,32,1)
#undef BSTEP
            float s = Y[0] - X[0];
            float prev = Y[0];
#pragma unroll
            for (int j = 1; j < 32; j++) {
                s += Y[j] - fmaxf(X[j], prev);
                prev = Y[j];
            }
            float ssum = s, smax = s;
            ssum += __shfl_xor_sync(0xffffffffu, ssum, 1);
            smax  = fmaxf(smax, __shfl_xor_sync(0xffffffffu, smax, 1));
            ssum += __shfl_xor_sync(0xffffffffu, ssum, 2);
            smax  = fmaxf(smax, __shfl_xor_sync(0xffffffffu, smax, 2));
            if (comp == 0)
                iqePart[(size_t)(row0 + r) * 4 + colcta] = make_float2(ssum, smax);
        }
    }
}

// ---------------- fused input conversion + all prep ----------------
#define CONV_BLOCKS 65536
#define PREP_BLOCKS 3968

static __device__ __forceinline__ void wprep_body(
    int i, const float* __restrict__ W, int K, const float* __restrict__ s,
    __half* __restrict__ wt)
{
    int n = i / K, k = i % K;
    float v = W[(size_t)k * 512 + n];
    if (s) v *= s[k];
    wt[i] = __float2half_rn(v);
}

static __device__ __forceinline__ void ucprep_body(
    int blk, int tid, const float* __restrict__ W, const float* __restrict__ s,
    const float* __restrict__ t, const float* __restrict__ beta,
    float* __restrict__ u, float* __restrict__ c,
    float* __restrict__ ru, float* __restrict__ rc)
{
    const int half = tid >> 7;
    const int tt   = tid & 127;
    const int n    = blk * 2 + half;
    float us = 0.f, cs = 0.f;
    for (int k = tt; k < 512; k += 128) {
        float w = W[(size_t)k * 512 + n];
        us += s[k] * w;
        cs += t[k] * w;
    }
    ru[tid] = us; rc[tid] = cs;
    __syncthreads();
    for (int off = 64; off; off >>= 1) {
        if (tt < off) {
            ru[tid] += ru[tid + off];
            rc[tid] += rc[tid + off];
        }
        __syncthreads();
    }
    if (tt == 0) { u[n] = ru[tid]; c[n] = rc[tid] + beta[n]; }
}

__global__ __launch_bounds__(256)
void conv_prep(const float* __restrict__ obs, const float* __restrict__ gls,
               __half* __restrict__ a0out,
               const float* __restrict__ W0, const float* __restrict__ W1,
               const float* __restrict__ W2, const float* __restrict__ W3,
               const float* __restrict__ l0s, const float* __restrict__ l0b,
               const float* __restrict__ b1,
               const float* __restrict__ l1s, const float* __restrict__ l1b,
               const float* __restrict__ b2,
               const float* __restrict__ l2s, const float* __restrict__ l2b,
               const float* __restrict__ b3,
               __half* __restrict__ wt0, __half* __restrict__ wt1,
               __half* __restrict__ wt2, __half* __restrict__ wt3,
               float* __restrict__ u1, float* __restrict__ c1,
               float* __restrict__ u2, float* __restrict__ c2,
               float* __restrict__ u3, float* __restrict__ c3)
{
    __shared__ float ru[256], rc[256];
    const int tid = threadIdx.x;
    if (blockIdx.x < CONV_BLOCKS) {
        size_t i = (size_t)blockIdx.x * 256 + tid;
        float v = (i < (size_t)B_ROWS * 64) ? obs[i] : gls[i - (size_t)B_ROWS * 64];
        a0out[i] = __float2half_rn(v);
        return;
    }
    const int b = blockIdx.x - CONV_BLOCKS;
    if (b < 128) {
        wprep_body(b * 256 + tid, W0, 64, nullptr, wt0);
    } else if (b < 1152) {
        wprep_body((b - 128) * 256 + tid, W1, 512, l0s, wt1);
    } else if (b < 2176) {
        wprep_body((b - 1152) * 256 + tid, W2, 512, l1s, wt2);
    } else if (b < 3200) {
        wprep_body((b - 2176) * 256 + tid, W3, 512, l2s, wt3);
    } else if (b < 3456) {
        ucprep_body(b - 3200, tid, W1, l0s, l0b, b1, u1, c1, ru, rc);
    } else if (b < 3712) {
        ucprep_body(b - 3456, tid, W2, l1s, l1b, b2, u2, c2, ru, rc);
    } else {
        ucprep_body(b - 3712, tid, W3, l2s, l2b, b3, u3, c3, ru, rc);
    }
}

// ---------------- final IQE combine ----------------
__global__ __launch_bounds__(256)
void iqe_combine(const float2* __restrict__ part, const float* __restrict__ alpha_p,
                 float* __restrict__ out)
{
    int r = blockIdx.x * 256 + threadIdx.x;
    if (r >= B_ROWS) return;
    float2 p0 = part[(size_t)r * 4 + 0];
    float2 p1 = part[(size_t)r * 4 + 1];
    float2 p2 = part[(size_t)r * 4 + 2];
    float2 p3 = part[(size_t)r * 4 + 3];
    float ssum = (p0.x + p1.x) + (p2.x + p3.x);
    float smax = fmaxf(fmaxf(p0.y, p1.y), fmaxf(p2.y, p3.y));
    float a = 1.0f / (1.0f + expf(-alpha_p[0]));
    out[r] = a * (ssum * (1.0f / 16.0f)) + (1.0f - a) * smax;
}

// ---------------- launch ----------------
extern "C" void kernel_launch(void* const* d_in, const int* in_sizes, int n_in,
                              void* d_out, int out_size)
{
    const float* obs   = (const float*)d_in[0];
    const float* gls   = (const float*)d_in[1];
    const float* W0    = (const float*)d_in[2];
    const float* b0    = (const float*)d_in[3];
    const float* l0s   = (const float*)d_in[4];
    const float* l0b   = (const float*)d_in[5];
    const float* W1    = (const float*)d_in[6];
    const float* b1    = (const float*)d_in[7];
    const float* l1s   = (const float*)d_in[8];
    const float* l1b   = (const float*)d_in[9];
    const float* W2    = (const float*)d_in[10];
    const float* b2    = (const float*)d_in[11];
    const float* l2s   = (const float*)d_in[12];
    const float* l2b   = (const float*)d_in[13];
    const float* W3    = (const float*)d_in[14];
    const float* b3    = (const float*)d_in[15];
    const float* alpha = (const float*)d_in[16];

    __half *a0, *actA, *actB, *wt0, *wt1, *wt2, *wt3;
    float *u1, *c1, *u2, *c2, *u3, *c3;
    float4 *stA, *stB;
    float2 *part;
    cudaGetSymbolAddress((void**)&a0,   g_a0);
    cudaGetSymbolAddress((void**)&actA, g_actA);
    cudaGetSymbolAddress((void**)&actB, g_actB);
    cudaGetSymbolAddress((void**)&wt0,  g_wt0);
    cudaGetSymbolAddress((void**)&wt1,  g_wt1);
    cudaGetSymbolAddress((void**)&wt2,  g_wt2);
    cudaGetSymbolAddress((void**)&wt3,  g_wt3);
    cudaGetSymbolAddress((void**)&u1,   g_u1);
    cudaGetSymbolAddress((void**)&c1,   g_c1);
    cudaGetSymbolAddress((void**)&u2,   g_u2);
    cudaGetSymbolAddress((void**)&c2,   g_c2);
    cudaGetSymbolAddress((void**)&u3,   g_u3);
    cudaGetSymbolAddress((void**)&c3,   g_c3);
    cudaGetSymbolAddress((void**)&stA,  g_statA);
    cudaGetSymbolAddress((void**)&stB,  g_statB);
    cudaGetSymbolAddress((void**)&part, g_iqePart);

    cudaFuncSetAttribute(gemm_kernel<64,  true,  false, false>, cudaFuncAttributeMaxDynamicSharedMemorySize, SMEM_BYTES);
    cudaFuncSetAttribute(gemm_kernel<512, true,  true,  false>, cudaFuncAttributeMaxDynamicSharedMemorySize, SMEM_BYTES);
    cudaFuncSetAttribute(gemm_kernel<512, false, true,  true >, cudaFuncAttributeMaxDynamicSharedMemorySize, SMEM_BYTES);

    dim3 blk(256);
    dim3 grid((TOT_ROWS / 64) * 4);            // 16384

    // launch 0: input conversion + ALL weight/fold prep
    conv_prep<<<CONV_BLOCKS + PREP_BLOCKS, 256>>>(
        obs, gls, a0, W0, W1, W2, W3,
        l0s, l0b, b1, l1s, l1b, b2, l2s, l2b, b3,
        wt0, wt1, wt2, wt3, u1, c1, u2, c2, u3, c3);

    // launch 1: L0 (no fold), gelu + stats -> statA
    gemm_kernel<64, true, false, false><<<grid, blk, SMEM_BYTES>>>(
        a0, wt0, nullptr, b0, nullptr, (float2*)stA, actA, nullptr);

    // launch 2: L1, fold ln0
    gemm_kernel<512, true, true, false><<<grid, blk, SMEM_BYTES>>>(
        actA, wt1, u1, c1, stA, (float2*)stB, actB, nullptr);

    // launch 3 (ncu capture slot): L2, fold ln1
    gemm_kernel<512, true, true, false><<<grid, blk, SMEM_BYTES>>>(
        actB, wt2, u2, c2, stB, (float2*)stA, actA, nullptr);

    // launch 4: L3, fold ln2, paired rows, fused IQE -> partials
    gemm_kernel<512, false, true, true><<<(B_ROWS / 32) * 4, blk, SMEM_BYTES>>>(
        actA, wt3, u3, c3, stA, nullptr, nullptr, part);

    // launch 5
    iqe_combine<<<(B_ROWS + 255) / 256, 256>>>(part, alpha, (float*)d_out);
}

// round 13
// speedup vs baseline: 1.2520x; 1.2520x over previous
#include <cuda_runtime.h>
#include <cuda_fp16.h>
#include <cstdint>

#define B_ROWS   131072
#define TOT_ROWS 262144

// ---------------- scratch (device globals; no allocations) ----------------
__device__ __half  g_actA[(size_t)TOT_ROWS * 512];
__device__ __half  g_actB[(size_t)TOT_ROWS * 512];
__device__ __half  g_wt0[512 * 64];
__device__ __half  g_wt1[512 * 512];
__device__ __half  g_wt2[512 * 512];
__device__ __half  g_wt3[512 * 512];
__device__ float4  g_statA[(size_t)TOT_ROWS * 8];   // 16 float2 partials per row
__device__ float4  g_statB[(size_t)TOT_ROWS * 8];
__device__ float   g_u1[512], g_c1[512];
__device__ float   g_u2[512], g_c2[512];
__device__ float   g_u3[512], g_c3[512];
__device__ float2  g_iqePart[(size_t)B_ROWS * 4];   // (sum4, max4) per (row, colcta)

// ---------------- PTX helpers ----------------
static __device__ __forceinline__ uint32_t smem_u32(const void* p) {
    uint32_t a;
    asm("{ .reg .u64 t; cvta.to.shared.u64 t, %1; cvt.u32.u64 %0, t; }" : "=r"(a) : "l"(p));
    return a;
}
static __device__ __forceinline__ void cp16(uint32_t dst, const void* src) {
    asm volatile("cp.async.cg.shared.global [%0], [%1], 16;" :: "r"(dst), "l"(src));
}
static __device__ __forceinline__ void ldm_x4(uint32_t (&r)[4], uint32_t addr) {
    asm volatile("ldmatrix.sync.aligned.m8n8.x4.shared.b16 {%0,%1,%2,%3}, [%4];"
                 : "=r"(r[0]), "=r"(r[1]), "=r"(r[2]), "=r"(r[3]) : "r"(addr));
}
static __device__ __forceinline__ void mma_f16(float (&d)[4], const uint32_t (&a)[4],
                                               uint32_t b0, uint32_t b1) {
    asm volatile("mma.sync.aligned.m16n8k16.row.col.f32.f16.f16.f32 "
                 "{%0,%1,%2,%3}, {%4,%5,%6,%7}, {%8,%9}, {%0,%1,%2,%3};"
                 : "+f"(d[0]), "+f"(d[1]), "+f"(d[2]), "+f"(d[3])
                 : "r"(a[0]), "r"(a[1]), "r"(a[2]), "r"(a[3]), "r"(b0), "r"(b1));
}
// gelu(x) = x * sigmoid(2 * sqrt(2/pi) * (x + 0.044715 x^3))   (tanh form)
static __device__ __forceinline__ float gelu_f(float x) {
    float u = 0.7978845608028654f * x * (1.0f + 0.044715f * x * x);
    return x / (1.0f + __expf(-2.0f * u));
}
// swizzled byte offset within a [rows][32 f16 = 64B] tile (conflict-free ldmatrix)
static __device__ __forceinline__ uint32_t swz(int row, int seg) {
    return (uint32_t)(row * 64 + ((seg ^ ((row >> 1) & 3)) << 4));
}

// ---------------- smem layout ----------------
// mainloop: 6-slot ring, slot (16KB): A @ 0 (8KB: 128 rows x 64B), W @ +8192 (8KB)
// paired epilogue: phi tile [128][132] f32 (67584B) + fold arrays (reuses ring)
#define SLOT_BYTES 16384
#define SMEM_BYTES (6 * SLOT_BYTES + 128)
#define L0_SMEM    (2 * SLOT_BYTES + 128)

// ---------------- fp16 single-MMA GEMM with folded LayerNorm ----------------
// CTA: 128 rows x 128 cols, 256 threads, warp grid 2(m) x 4(n), warp tile 64x32.
// occ 2. Ring of 6 K=32 slots; ONE barrier per TWO slots (64 MMAs/warp between
// barriers). All ldmatrix/cp.async addresses precomputed; h=1 offsets = h0 ^ 32.
// FOLD: output = inv*(g@W'') - (m*inv)*u + c.
// ACT:  gelu, fp16 activation out + per-row partial stats.
// PAIRED (final layer): local rows 0-63 = phi_s, 64-127 = phi_g of the SAME 64
// batch rows; epilogue computes IQE per (pair, component) in-CTA.
template<int KDIM, bool ACT, bool FOLD, bool PAIRED>
__global__ __launch_bounds__(256, 2)
void gemm_kernel(const __half* __restrict__ Aact, const __half* __restrict__ Wt,
                 const float* __restrict__ uvec, const float* __restrict__ cvec,
                 const float4* __restrict__ statsIn, float2* __restrict__ statsOut,
                 __half* __restrict__ Oact, float2* __restrict__ iqePart)
{
    extern __shared__ char smraw[];
    char* smal = (char*)(((uintptr_t)smraw + 127) & ~(uintptr_t)127);
    const uint32_t sb = smem_u32(smal);

    const int tid  = threadIdx.x;
    const int lane = tid & 31;
    const int wid  = tid >> 5;
    const int wm   = wid >> 2;                 // 0..1 -> rows wm*64
    const int wn   = wid & 3;                  // 0..3 -> cols wn*32
    const int rowTile = blockIdx.x >> 2;
    const int colcta  = blockIdx.x & 3;
    const int row0 = PAIRED ? rowTile * 64 : rowTile * 128;
    const int col0 = colcta * 128;

    constexpr int NS = KDIM / 32;              // 16

    float acc[4][4][4];
#pragma unroll
    for (int mt = 0; mt < 4; mt++)
#pragma unroll
        for (int nt = 0; nt < 4; nt++)
#pragma unroll
            for (int j = 0; j < 4; j++) acc[mt][nt][j] = 0.f;

    // -------- precomputed loader state --------
    const int rA  = tid >> 2;
    const int sgA = tid & 3;
    const uint32_t dstA0 = swz(rA, sgA);
    const uint32_t dstA1 = swz(rA + 64, sgA);
    const uint32_t dstW0 = 8192u + dstA0;
    const uint32_t dstW1 = 8192u + dstA1;
    size_t growA0, growA1;
    if constexpr (PAIRED) {
        growA0 = (size_t)(row0 + rA);
        growA1 = (size_t)B_ROWS + row0 + rA;
    } else {
        growA0 = (size_t)(row0 + rA);
        growA1 = growA0 + 64;
    }
    const __half* gA0 = Aact + growA0 * KDIM + sgA * 8;
    const __half* gA1 = Aact + growA1 * KDIM + sgA * 8;
    const __half* gW0 = Wt + (size_t)(col0 + rA) * KDIM + sgA * 8;
    const __half* gW1 = gW0 + (size_t)64 * KDIM;

    // -------- precomputed ldmatrix offsets (h=1 = h0 ^ 32) --------
    const int ar   = lane & 15;
    const int aseg = lane >> 4;
    const int br   = (lane & 7) + ((lane >> 4) << 3);
    const int bseg = (lane >> 3) & 1;
    uint32_t offA[4], offB[2];
#pragma unroll
    for (int mt = 0; mt < 4; mt++) offA[mt] = swz(wm * 64 + mt * 16 + ar, aseg);
#pragma unroll
    for (int p = 0; p < 2; p++)    offB[p]  = 8192u + swz(wn * 32 + p * 16 + br, bseg);

#define LOAD_SLOT(slot)                                                     \
    do {                                                                    \
        uint32_t stb_ = sb + (uint32_t)(slot) * SLOT_BYTES;                 \
        cp16(stb_ + dstA0, gA0); cp16(stb_ + dstA1, gA1);                   \
        cp16(stb_ + dstW0, gW0); cp16(stb_ + dstW1, gW1);                   \
        asm volatile("cp.async.commit_group;");                             \
        gA0 += 32; gA1 += 32; gW0 += 32; gW1 += 32;                         \
    } while (0)

    // prologue: 4 groups
#pragma unroll
    for (int s = 0; s < 4; s++) LOAD_SLOT(s);

    int cslot = 0;
    int lslot = 4;
#pragma unroll 1
    for (int it = 0; it < NS / 2; it++) {
        asm volatile("cp.async.wait_group 2;");
        __syncthreads();

        const int s4 = 2 * it + 4;
        if (s4 < NS)     LOAD_SLOT(lslot);
        else             asm volatile("cp.async.commit_group;");
        lslot = (lslot + 1 == 6) ? 0 : lslot + 1;
        if (s4 + 1 < NS) LOAD_SLOT(lslot);
        else             asm volatile("cp.async.commit_group;");
        lslot = (lslot + 1 == 6) ? 0 : lslot + 1;

#pragma unroll
        for (int u = 0; u < 2; u++) {
            const uint32_t stb = sb + (uint32_t)cslot * SLOT_BYTES;
#pragma unroll
            for (int h = 0; h < 2; h++) {
                const uint32_t hb = (uint32_t)h << 5;
                uint32_t a[4][4], b[2][4];
#pragma unroll
                for (int mt = 0; mt < 4; mt++) ldm_x4(a[mt], stb + (offA[mt] ^ hb));
#pragma unroll
                for (int p = 0; p < 2; p++)    ldm_x4(b[p],  stb + (offB[p]  ^ hb));
#pragma unroll
                for (int p = 0; p < 2; p++)
#pragma unroll
                    for (int q = 0; q < 2; q++)
#pragma unroll
                        for (int mt = 0; mt < 4; mt++)
                            mma_f16(acc[mt][2 * p + q], a[mt], b[p][2 * q], b[p][2 * q + 1]);
            }
            cslot = (cslot + 1 == 6) ? 0 : cslot + 1;
        }
    }
#undef LOAD_SLOT
    __syncthreads();   // release ring smem for epilogue

    // ---------------- epilogue ----------------
    float* base = (float*)smal;
    float* sInv = PAIRED ? (float*)(smal + 67584) : base;   // [128]
    float* sMi  = sInv + 128;
    float* sU   = sMi + 128;
    float* sC   = sU + 128;

    if constexpr (FOLD) {
        if (tid < 128) {
            size_t grow;
            if constexpr (PAIRED)
                grow = (tid < 64) ? (size_t)(row0 + tid)
                                  : (size_t)B_ROWS + row0 + (tid - 64);
            else
                grow = (size_t)(row0 + tid);
            const float4* sp = statsIn + grow * 8;
            float ss = 0.f, sq = 0.f;
#pragma unroll
            for (int i = 0; i < 8; i++) {
                float4 v = sp[i];
                ss += v.x + v.z;
                sq += v.y + v.w;
            }
            float m   = ss * (1.0f / 512.0f);
            float var = fmaxf(sq * (1.0f / 512.0f) - m * m, 0.0f);
            float inv = rsqrtf(var + 1e-6f);
            sInv[tid] = inv;
            sMi[tid]  = m * inv;
        }
    }
    if (tid >= 128) {
        sU[tid - 128] = FOLD ? uvec[col0 + tid - 128] : 0.0f;
        sC[tid - 128] = cvec[col0 + tid - 128];
    }
    __syncthreads();

#pragma unroll
    for (int mt = 0; mt < 4; mt++) {
#pragma unroll
        for (int dp = 0; dp < 2; dp++) {
            const int rl   = wm * 64 + mt * 16 + dp * 8 + (lane >> 2);
            const float inv = FOLD ? sInv[rl] : 1.0f;
            const float mi  = FOLD ? sMi[rl]  : 0.0f;
            float gs = 0.f, gq = 0.f;
            size_t grow = (size_t)(row0 + rl);   // used by ACT path only
#pragma unroll
            for (int nt = 0; nt < 4; nt++) {
                const int cl = wn * 32 + nt * 8 + 2 * (lane & 3);
                float z0 = inv * acc[mt][nt][2 * dp + 0] - mi * sU[cl]     + sC[cl];
                float z1 = inv * acc[mt][nt][2 * dp + 1] - mi * sU[cl + 1] + sC[cl + 1];
                if constexpr (PAIRED) {
                    // stage phi in [row][i][comp] layout: conflict-free comp gathers
                    base[rl * 132 + (cl & 31) * 4 + (cl >> 5)]       = z0;
                    base[rl * 132 + ((cl & 31) + 1) * 4 + (cl >> 5)] = z1;
                } else if constexpr (ACT) {
                    float g0 = gelu_f(z0), g1 = gelu_f(z1);
                    gs += g0 + g1;
                    gq += g0 * g0 + g1 * g1;
                    __half2 hv = __floats2half2_rn(g0, g1);
                    *(__half2*)(Oact + grow * 512 + col0 + cl) = hv;
                }
            }
            if constexpr (ACT && !PAIRED) {
                gs += __shfl_xor_sync(0xffffffffu, gs, 1);
                gs += __shfl_xor_sync(0xffffffffu, gs, 2);
                gq += __shfl_xor_sync(0xffffffffu, gq, 1);
                gq += __shfl_xor_sync(0xffffffffu, gq, 2);
                if ((lane & 3) == 0)
                    statsOut[grow * 16 + (size_t)(colcta * 4 + wn)] = make_float2(gs, gq);
            }
        }
    }

    if constexpr (PAIRED) {
        __syncthreads();
        // one thread per (pair row r, component comp); 4 comps = lanes sharing r
        const int r    = tid >> 2;       // 0..63
        const int comp = tid & 3;
        const float* xs  = base + r * 132 + comp;
        const float* gs_ = base + (64 + r) * 132 + comp;
        float X[32], Y[32];
#pragma unroll
        for (int i = 0; i < 32; i++) {
            float xv = xs[i * 4];
            X[i] = xv;
            Y[i] = fmaxf(xv, gs_[i * 4]);
        }
#define BSTEP(V, KK, J)                                                   \
        _Pragma("unroll")                                                 \
        for (int i = 0; i < 32; i++) {                                    \
            int l = i ^ (J);                                              \
            if (l > i) {                                                  \
                bool up = ((i & (KK)) == 0);                              \
                float a_ = V[i], b_ = V[l];                               \
                float lo = fminf(a_, b_), hi = fmaxf(a_, b_);             \
                V[i] = up ? lo : hi;  V[l] = up ? hi : lo;                \
            }                                                             \
        }
        BSTEP(X,2,1) BSTEP(X,4,2) BSTEP(X,4,1) BSTEP(X,8,4) BSTEP(X,8,2) BSTEP(X,8,1)
        BSTEP(X,16,8) BSTEP(X,16,4) BSTEP(X,16,2) BSTEP(X,16,1)
        BSTEP(X,32,16) BSTEP(X,32,8) BSTEP(X,32,4) BSTEP(X,32,2) BSTEP(X,32,1)
        BSTEP(Y,2,1) BSTEP(Y,4,2) BSTEP(Y,4,1) BSTEP(Y,8,4) BSTEP(Y,8,2) BSTEP(Y,8,1)
        BSTEP(Y,16,8) BSTEP(Y,16,4) BSTEP(Y,16,2) BSTEP(Y,16,1)
        BSTEP(Y,32,16) BSTEP(Y,32,8) BSTEP(Y,32,4) BSTEP(Y,32,2) BSTEP(Y,32,1)
#undef BSTEP
        float s = Y[0] - X[0];
        float prev = Y[0];
#pragma unroll
        for (int j = 1; j < 32; j++) {
            s += Y[j] - fmaxf(X[j], prev);
            prev = Y[j];
        }
        float ssum = s, smax = s;
        ssum += __shfl_xor_sync(0xffffffffu, ssum, 1);
        smax  = fmaxf(smax, __shfl_xor_sync(0xffffffffu, smax, 1));
        ssum += __shfl_xor_sync(0xffffffffu, ssum, 2);
        smax  = fmaxf(smax, __shfl_xor_sync(0xffffffffu, smax, 2));
        if (comp == 0)
            iqePart[(size_t)(row0 + r) * 4 + colcta] = make_float2(ssum, smax);
    }
}

// ---------------- L0: fused f32->fp16 conversion + GEMM (K=64) ----------------
// CTA 128 rows x 128 cols, same warp layout/epilogue as the generic ACT kernel.
// A is read as f32 from obs/goals and converted in-register into the swizzled
// smem slots (no g_a0 round trip); W comes via cp.async from prepped wt0.
__global__ __launch_bounds__(256, 2)
void l0_kernel(const float* __restrict__ obs, const float* __restrict__ gls,
               const __half* __restrict__ Wt, const float* __restrict__ bias,
               float2* __restrict__ statsOut, __half* __restrict__ Oact)
{
    extern __shared__ char smraw[];
    char* smal = (char*)(((uintptr_t)smraw + 127) & ~(uintptr_t)127);
    const uint32_t sb = smem_u32(smal);

    const int tid  = threadIdx.x;
    const int lane = tid & 31;
    const int wid  = tid >> 5;
    const int wm   = wid >> 2;
    const int wn   = wid & 3;
    const int row0 = (blockIdx.x >> 2) * 128;
    const int colcta = blockIdx.x & 3;
    const int col0 = colcta * 128;

    // W: 2 slots x 512 segs, 2 per thread per slot, via cp.async
#pragma unroll
    for (int slot = 0; slot < 2; slot++) {
#pragma unroll
        for (int i = 0; i < 2; i++) {
            int idx = i * 256 + tid;
            int n = idx >> 2, sg = idx & 3;
            cp16(sb + (uint32_t)slot * SLOT_BYTES + 8192u + swz(n, sg),
                 Wt + (size_t)(col0 + n) * 64 + slot * 32 + sg * 8);
        }
    }
    asm volatile("cp.async.commit_group;");

    // A: convert f32 -> fp16 into swizzled smem (4 segs per thread)
#pragma unroll
    for (int j = 0; j < 4; j++) {
        int idx  = j * 256 + tid;            // 0..1023
        int slot = idx >> 9;
        int rem  = idx & 511;
        int r    = rem >> 2, sg = rem & 3;
        int k0   = slot * 32 + sg * 8;
        size_t grow = (size_t)(row0 + r);
        const float* src = (grow < B_ROWS) ? (obs + grow * 64)
                                           : (gls + (grow - B_ROWS) * 64);
        float4 v0 = *(const float4*)(src + k0);
        float4 v1 = *(const float4*)(src + k0 + 4);
        __half2 h[4];
        h[0] = __floats2half2_rn(v0.x, v0.y);
        h[1] = __floats2half2_rn(v0.z, v0.w);
        h[2] = __floats2half2_rn(v1.x, v1.y);
        h[3] = __floats2half2_rn(v1.z, v1.w);
        *(uint4*)(smal + slot * SLOT_BYTES + swz(r, sg)) = *(const uint4*)h;
    }

    asm volatile("cp.async.wait_group 0;");
    __syncthreads();

    float acc[4][4][4];
#pragma unroll
    for (int mt = 0; mt < 4; mt++)
#pragma unroll
        for (int nt = 0; nt < 4; nt++)
#pragma unroll
            for (int j = 0; j < 4; j++) acc[mt][nt][j] = 0.f;

    const int ar   = lane & 15;
    const int aseg = lane >> 4;
    const int br   = (lane & 7) + ((lane >> 4) << 3);
    const int bseg = (lane >> 3) & 1;
    uint32_t offA[4], offB[2];
#pragma unroll
    for (int mt = 0; mt < 4; mt++) offA[mt] = swz(wm * 64 + mt * 16 + ar, aseg);
#pragma unroll
    for (int p = 0; p < 2; p++)    offB[p]  = 8192u + swz(wn * 32 + p * 16 + br, bseg);

#pragma unroll
    for (int s = 0; s < 2; s++) {
        const uint32_t stb = sb + (uint32_t)s * SLOT_BYTES;
#pragma unroll
        for (int h = 0; h < 2; h++) {
            const uint32_t hb = (uint32_t)h << 5;
            uint32_t a[4][4], b[2][4];
#pragma unroll
            for (int mt = 0; mt < 4; mt++) ldm_x4(a[mt], stb + (offA[mt] ^ hb));
#pragma unroll
            for (int p = 0; p < 2; p++)    ldm_x4(b[p],  stb + (offB[p]  ^ hb));
#pragma unroll
            for (int p = 0; p < 2; p++)
#pragma unroll
                for (int q = 0; q < 2; q++)
#pragma unroll
                    for (int mt = 0; mt < 4; mt++)
                        mma_f16(acc[mt][2 * p + q], a[mt], b[p][2 * q], b[p][2 * q + 1]);
        }
    }
    __syncthreads();

    // epilogue: bias + gelu + fp16 out + stats (no fold)
    float* sC = (float*)smal;                // [128]
    if (tid < 128) sC[tid] = bias[col0 + tid];
    __syncthreads();

#pragma unroll
    for (int mt = 0; mt < 4; mt++) {
#pragma unroll
        for (int dp = 0; dp < 2; dp++) {
            const int rl = wm * 64 + mt * 16 + dp * 8 + (lane >> 2);
            const size_t grow = (size_t)(row0 + rl);
            float gs = 0.f, gq = 0.f;
#pragma unroll
            for (int nt = 0; nt < 4; nt++) {
                const int cl = wn * 32 + nt * 8 + 2 * (lane & 3);
                float z0 = acc[mt][nt][2 * dp + 0] + sC[cl];
                float z1 = acc[mt][nt][2 * dp + 1] + sC[cl + 1];
                float g0 = gelu_f(z0), g1 = gelu_f(z1);
                gs += g0 + g1;
                gq += g0 * g0 + g1 * g1;
                __half2 hv = __floats2half2_rn(g0, g1);
                *(__half2*)(Oact + grow * 512 + col0 + cl) = hv;
            }
            gs += __shfl_xor_sync(0xffffffffu, gs, 1);
            gs += __shfl_xor_sync(0xffffffffu, gs, 2);
            gq += __shfl_xor_sync(0xffffffffu, gq, 1);
            gq += __shfl_xor_sync(0xffffffffu, gq, 2);
            if ((lane & 3) == 0)
                statsOut[grow * 16 + (size_t)(colcta * 4 + wn)] = make_float2(gs, gq);
        }
    }
}

// ---------------- prep: all weight transposes + fold vectors ----------------
#define PREP_BLOCKS 3968

static __device__ __forceinline__ void wprep_body(
    int i, const float* __restrict__ W, int K, const float* __restrict__ s,
    __half* __restrict__ wt)
{
    int n = i / K, k = i % K;
    float v = W[(size_t)k * 512 + n];
    if (s) v *= s[k];
    wt[i] = __float2half_rn(v);
}

static __device__ __forceinline__ void ucprep_body(
    int blk, int tid, const float* __restrict__ W, const float* __restrict__ s,
    const float* __restrict__ t, const float* __restrict__ beta,
    float* __restrict__ u, float* __restrict__ c,
    float* __restrict__ ru, float* __restrict__ rc)
{
    const int half = tid >> 7;
    const int tt   = tid & 127;
    const int n    = blk * 2 + half;
    float us = 0.f, cs = 0.f;
    for (int k = tt; k < 512; k += 128) {
        float w = W[(size_t)k * 512 + n];
        us += s[k] * w;
        cs += t[k] * w;
    }
    ru[tid] = us; rc[tid] = cs;
    __syncthreads();
    for (int off = 64; off; off >>= 1) {
        if (tt < off) {
            ru[tid] += ru[tid + off];
            rc[tid] += rc[tid + off];
        }
        __syncthreads();
    }
    if (tt == 0) { u[n] = ru[tid]; c[n] = rc[tid] + beta[n]; }
}

__global__ __launch_bounds__(256)
void prep_all(const float* __restrict__ W0, const float* __restrict__ W1,
              const float* __restrict__ W2, const float* __restrict__ W3,
              const float* __restrict__ l0s, const float* __restrict__ l0b,
              const float* __restrict__ b1,
              const float* __restrict__ l1s, const float* __restrict__ l1b,
              const float* __restrict__ b2,
              const float* __restrict__ l2s, const float* __restrict__ l2b,
              const float* __restrict__ b3,
              __half* __restrict__ wt0, __half* __restrict__ wt1,
              __half* __restrict__ wt2, __half* __restrict__ wt3,
              float* __restrict__ u1, float* __restrict__ c1,
              float* __restrict__ u2, float* __restrict__ c2,
              float* __restrict__ u3, float* __restrict__ c3)
{
    __shared__ float ru[256], rc[256];
    const int b   = blockIdx.x;
    const int tid = threadIdx.x;
    if (b < 128) {
        wprep_body(b * 256 + tid, W0, 64, nullptr, wt0);
    } else if (b < 1152) {
        wprep_body((b - 128) * 256 + tid, W1, 512, l0s, wt1);
    } else if (b < 2176) {
        wprep_body((b - 1152) * 256 + tid, W2, 512, l1s, wt2);
    } else if (b < 3200) {
        wprep_body((b - 2176) * 256 + tid, W3, 512, l2s, wt3);
    } else if (b < 3456) {
        ucprep_body(b - 3200, tid, W1, l0s, l0b, b1, u1, c1, ru, rc);
    } else if (b < 3712) {
        ucprep_body(b - 3456, tid, W2, l1s, l1b, b2, u2, c2, ru, rc);
    } else {
        ucprep_body(b - 3712, tid, W3, l2s, l2b, b3, u3, c3, ru, rc);
    }
}

// ---------------- final IQE combine ----------------
__global__ __launch_bounds__(256)
void iqe_combine(const float2* __restrict__ part, const float* __restrict__ alpha_p,
                 float* __restrict__ out)
{
    int r = blockIdx.x * 256 + threadIdx.x;
    if (r >= B_ROWS) return;
    float2 p0 = part[(size_t)r * 4 + 0];
    float2 p1 = part[(size_t)r * 4 + 1];
    float2 p2 = part[(size_t)r * 4 + 2];
    float2 p3 = part[(size_t)r * 4 + 3];
    float ssum = (p0.x + p1.x) + (p2.x + p3.x);
    float smax = fmaxf(fmaxf(p0.y, p1.y), fmaxf(p2.y, p3.y));
    float a = 1.0f / (1.0f + expf(-alpha_p[0]));
    out[r] = a * (ssum * (1.0f / 16.0f)) + (1.0f - a) * smax;
}

// ---------------- launch ----------------
extern "C" void kernel_launch(void* const* d_in, const int* in_sizes, int n_in,
                              void* d_out, int out_size)
{
    const float* obs   = (const float*)d_in[0];
    const float* gls   = (const float*)d_in[1];
    const float* W0    = (const float*)d_in[2];
    const float* b0    = (const float*)d_in[3];
    const float* l0s   = (const float*)d_in[4];
    const float* l0b   = (const float*)d_in[5];
    const float* W1    = (const float*)d_in[6];
    const float* b1    = (const float*)d_in[7];
    const float* l1s   = (const float*)d_in[8];
    const float* l1b   = (const float*)d_in[9];
    const float* W2    = (const float*)d_in[10];
    const float* b2    = (const float*)d_in[11];
    const float* l2s   = (const float*)d_in[12];
    const float* l2b   = (const float*)d_in[13];
    const float* W3    = (const float*)d_in[14];
    const float* b3    = (const float*)d_in[15];
    const float* alpha = (const float*)d_in[16];

    __half *actA, *actB, *wt0, *wt1, *wt2, *wt3;
    float *u1, *c1, *u2, *c2, *u3, *c3;
    float4 *stA, *stB;
    float2 *part;
    cudaGetSymbolAddress((void**)&actA, g_actA);
    cudaGetSymbolAddress((void**)&actB, g_actB);
    cudaGetSymbolAddress((void**)&wt0,  g_wt0);
    cudaGetSymbolAddress((void**)&wt1,  g_wt1);
    cudaGetSymbolAddress((void**)&wt2,  g_wt2);
    cudaGetSymbolAddress((void**)&wt3,  g_wt3);
    cudaGetSymbolAddress((void**)&u1,   g_u1);
    cudaGetSymbolAddress((void**)&c1,   g_c1);
    cudaGetSymbolAddress((void**)&u2,   g_u2);
    cudaGetSymbolAddress((void**)&c2,   g_c2);
    cudaGetSymbolAddress((void**)&u3,   g_u3);
    cudaGetSymbolAddress((void**)&c3,   g_c3);
    cudaGetSymbolAddress((void**)&stA,  g_statA);
    cudaGetSymbolAddress((void**)&stB,  g_statB);
    cudaGetSymbolAddress((void**)&part, g_iqePart);

    cudaFuncSetAttribute(gemm_kernel<512, true,  true,  false>, cudaFuncAttributeMaxDynamicSharedMemorySize, SMEM_BYTES);
    cudaFuncSetAttribute(gemm_kernel<512, false, true,  true >, cudaFuncAttributeMaxDynamicSharedMemorySize, SMEM_BYTES);
    cudaFuncSetAttribute(l0_kernel, cudaFuncAttributeMaxDynamicSharedMemorySize, L0_SMEM);

    dim3 blk(256);
    dim3 grid((TOT_ROWS / 128) * 4);           // 8192

    // launch 0: ALL weight/fold prep
    prep_all<<<PREP_BLOCKS, 256>>>(W0, W1, W2, W3,
                                   l0s, l0b, b1, l1s, l1b, b2, l2s, l2b, b3,
                                   wt0, wt1, wt2, wt3, u1, c1, u2, c2, u3, c3);

    // launch 1: L0 with fused f32->fp16 conversion, gelu + stats -> statA
    l0_kernel<<<grid, blk, L0_SMEM>>>(obs, gls, wt0, b0, (float2*)stA, actA);

    // launch 2: L1, fold ln0
    gemm_kernel<512, true, true, false><<<grid, blk, SMEM_BYTES>>>(
        actA, wt1, u1, c1, stA, (float2*)stB, actB, nullptr);

    // launch 3 (ncu capture slot): L2, fold ln1
    gemm_kernel<512, true, true, false><<<grid, blk, SMEM_BYTES>>>(
        actB, wt2, u2, c2, stB, (float2*)stA, actA, nullptr);

    // launch 4: L3, fold ln2, paired rows, fused IQE -> partials
    gemm_kernel<512, false, true, true><<<(B_ROWS / 64) * 4, blk, SMEM_BYTES>>>(
        actA, wt3, u3, c3, stA, nullptr, nullptr, part);

    // launch 5
    iqe_combine<<<(B_ROWS + 255) / 256, 256>>>(part, alpha, (float*)d_out);
}